// round 14
// baseline (speedup 1.0000x reference)
#include <cuda_runtime.h>
#include <cuda_bf16.h>
#include <cstdint>

// ---------------------------------------------------------------------------
// CapsuleNetwork forward, SINGLE kernel launch:
//  per block (c, 2 conv rows = 40 k):
//   - in-smem conv for its own xf tile
//   - stream W1[j, 40k, 8m, 32c] (327KB/block), c-reduce -> ws smem
//   - GEMM [64b x 64jm] over 40 k -> g_part[b][kt][jm]
//   - release: threadfence + atomicAdd epoch counter
//  blocks 0..63: spin until all 320 GEMMs of this replay done, then finalize
//  batch b=bid: contiguous reduce + squash + digit caps + routing(3) -> out.
//  Counter is monotonic (+320 per replay) -> no reset, graph-replay safe.
//  All reductions fixed-order -> deterministic.
// ---------------------------------------------------------------------------

#define B_SZ 64
#define IN_UNITS 12800      // 32*20*20
#define KT 40               // k per tile = 2 rows x 20
#define NKT 320             // 12800 / 40

__device__ float g_part[B_SZ * NKT * 64];    // 5.24 MB [b][kt][jm]
__device__ int   g_cnt;                      // monotonic epoch counter

// dynamic smem layout (floats)
#define SM_IMG   0                    // [64][284]  10 rows x 28 + pad
#define SM_XST   18176                // [40][68]   xf tile transposed [kk][b]
#define SM_WS    20896                // [40][68]   wsum tile [kk][jm]
#define SM_WSM   23616                // [82]       conv weights + bias
#define SM_TOTAL 23698                // floats -> 94792 bytes

__global__ __launch_bounds__(512) void mega_kernel(
    const float* __restrict__ x, const float* __restrict__ w,
    const float* __restrict__ bias, const float* __restrict__ W1,
    const float* __restrict__ W2, float* __restrict__ out)
{
    extern __shared__ float sm[];
    float* img = sm + SM_IMG;
    float* xsT = sm + SM_XST;
    float* ws  = sm + SM_WS;
    float* wsm = sm + SM_WSM;

    __shared__ int target_s;

    int bid = blockIdx.x;        // 0..319 ; k0 = bid*40
    int t = threadIdx.x;         // 0..511
    int c = bid / 10;            // conv channel
    int y0 = (bid % 10) * 2;     // first of 2 output rows

    const float4* __restrict__ Wv = (const float4*)W1;
    size_t base0 = (size_t)bid * 2560;          // f4 offset, j=0

    // ---- issue first stream batch early (DRAM busy during conv) ----
    float4 cur[5], nxt[5];
    #pragma unroll
    for (int q = 0; q < 5; q++) cur[q] = Wv[base0 + q * 512 + t];

    // ---- cooperative image rows load: rows y0..y0+9, all 64 b ----
    {
        const float* xb = x + y0 * 28;
        for (int i = t; i < 4480; i += 512) {
            int bb = i / 70, off = (i % 70) * 4;
            *(float4*)&img[bb * 284 + off] = *(const float4*)&xb[bb * 784 + off];
        }
    }
    if (t < 81) wsm[t] = w[c * 81 + t];
    if (t == 81) wsm[81] = bias[c];
    __syncthreads();

    // ---- conv: thread = (b = t>>3, yl = (t>>2)&1, xq = t&3), 5 outputs ----
    {
        int b = t >> 3, yl = (t >> 2) & 1, x0 = (t & 3) * 5;
        float bv = wsm[81];
        float a0 = 0.f, a1 = 0.f, a2 = 0.f, a3 = 0.f, a4 = 0.f;
        const float* ib = &img[b * 284 + yl * 28 + x0];
        #pragma unroll
        for (int i = 0; i < 9; i++) {
            float wr[9];
            #pragma unroll
            for (int jj = 0; jj < 9; jj++) wr[jj] = wsm[i * 9 + jj];
            float xr[13];
            #pragma unroll
            for (int u = 0; u < 13; u++) xr[u] = ib[i * 28 + u];
            #pragma unroll
            for (int jj = 0; jj < 9; jj++) {
                a0 = fmaf(xr[0 + jj], wr[jj], a0);
                a1 = fmaf(xr[1 + jj], wr[jj], a1);
                a2 = fmaf(xr[2 + jj], wr[jj], a2);
                a3 = fmaf(xr[3 + jj], wr[jj], a3);
                a4 = fmaf(xr[4 + jj], wr[jj], a4);
            }
        }
        int kk0 = yl * 20 + x0;
        xsT[(kk0 + 0) * 68 + b] = fmaxf(a0 + bv, 0.f);
        xsT[(kk0 + 1) * 68 + b] = fmaxf(a1 + bv, 0.f);
        xsT[(kk0 + 2) * 68 + b] = fmaxf(a2 + bv, 0.f);
        xsT[(kk0 + 3) * 68 + b] = fmaxf(a3 + bv, 0.f);
        xsT[(kk0 + 4) * 68 + b] = fmaxf(a4 + bv, 0.f);
    }

    // ---- W1 stream, 8 j batches, prefetch-pipelined; c-reduce -> ws ----
    int lanec = t & 7;
    #pragma unroll
    for (int j = 0; j < 8; j++) {
        if (j < 7) {
            size_t nb = base0 + (size_t)(j + 1) * 819200;
            #pragma unroll
            for (int q = 0; q < 5; q++) nxt[q] = Wv[nb + q * 512 + t];
        }
        #pragma unroll
        for (int q = 0; q < 5; q++) {
            float p = (cur[q].x + cur[q].y) + (cur[q].z + cur[q].w);
            p += __shfl_xor_sync(0xffffffffu, p, 1);
            p += __shfl_xor_sync(0xffffffffu, p, 2);
            p += __shfl_xor_sync(0xffffffffu, p, 4);
            if (lanec == 0) {
                int r = (q * 512 + t) >> 3;        // kk*8 + m
                ws[(r >> 3) * 68 + j * 8 + (r & 7)] = p;
            }
        }
        if (j < 7) {
            #pragma unroll
            for (int q = 0; q < 5; q++) cur[q] = nxt[q];
        }
    }
    __syncthreads();

    // ---- GEMM [64b x 64jm] over 40 k ----
    {
        int bq  = t >> 5;     // 0..15 -> b = 4*bq..
        int jm2 = t & 31;     // 0..31 -> jm = 2*jm2..

        float a0 = 0.f, a1 = 0.f, a2 = 0.f, a3 = 0.f;
        float a4 = 0.f, a5 = 0.f, a6 = 0.f, a7 = 0.f;

        #pragma unroll
        for (int kk = 0; kk < KT; kk++) {
            float4 xv = *(const float4*)&xsT[kk * 68 + bq * 4];
            float2 wv = *(const float2*)&ws[kk * 68 + jm2 * 2];
            a0 = fmaf(xv.x, wv.x, a0);
            a1 = fmaf(xv.y, wv.x, a1);
            a2 = fmaf(xv.z, wv.x, a2);
            a3 = fmaf(xv.w, wv.x, a3);
            a4 = fmaf(xv.x, wv.y, a4);
            a5 = fmaf(xv.y, wv.y, a5);
            a6 = fmaf(xv.z, wv.y, a6);
            a7 = fmaf(xv.w, wv.y, a7);
        }

        // g_part layout [b][kt][jm] : index = b*20480 + bid*64 + jm
        int col = jm2 * 2;
        float* dst = &g_part[(size_t)bid * 64 + col];
        dst[(size_t)(bq * 4 + 0) * 20480]     = a0;
        dst[(size_t)(bq * 4 + 1) * 20480]     = a1;
        dst[(size_t)(bq * 4 + 2) * 20480]     = a2;
        dst[(size_t)(bq * 4 + 3) * 20480]     = a3;
        dst[(size_t)(bq * 4 + 0) * 20480 + 1] = a4;
        dst[(size_t)(bq * 4 + 1) * 20480 + 1] = a5;
        dst[(size_t)(bq * 4 + 2) * 20480 + 1] = a6;
        dst[(size_t)(bq * 4 + 3) * 20480 + 1] = a7;
    }

    // ---- release: make g_part writes visible, bump epoch counter ----
    __threadfence();
    __syncthreads();
    if (t == 0) {
        int old = atomicAdd(&g_cnt, 1);
        target_s = old - (old % NKT) + NKT;   // end-of-epoch value
    }
    __syncthreads();

    if (bid >= B_SZ) return;                  // only blocks 0..63 finalize

    // ---- acquire: wait for all 320 GEMM slices of this replay ----
    if (t == 0) {
        while (*((volatile int*)&g_cnt) < target_s) { }
        __threadfence();
    }
    __syncthreads();

    // ---- finalize batch b = bid ----
    int b = bid;
    float* red  = sm;             // [32][68]
    float* ss   = sm + 2176;      // 64
    float* v1s  = sm + 2240;      // 64
    float* u2s  = sm + 2304;      // [80][17]
    float* vs   = sm + 3664;      // 160
    float* es   = sm + 3824;      // 80
    float* bs_s = sm + 3904;      // 80
    float* ids  = sm + 3984;      // 8

    // contiguous reduce of g_part[b][320][64]: thread=(g in 32, c4 in 16)
    {
        int c4 = t & 15, g = t >> 4;
        const float* src = &g_part[(size_t)b * 20480 + c4 * 4];
        float4 acc = make_float4(0.f, 0.f, 0.f, 0.f);
        #pragma unroll
        for (int q = 0; q < 10; q++) {
            float4 v = *(const float4*)&src[(size_t)(g + 32 * q) * 64];
            acc.x += v.x; acc.y += v.y; acc.z += v.z; acc.w += v.w;
        }
        red[g * 68 + c4 * 4 + 0] = acc.x;
        red[g * 68 + c4 * 4 + 1] = acc.y;
        red[g * 68 + c4 * 4 + 2] = acc.z;
        red[g * 68 + c4 * 4 + 3] = acc.w;
    }
    __syncthreads();
    if (t < 64) {
        float s = 0.f;
        #pragma unroll
        for (int i = 0; i < 32; i++) s += red[i * 68 + t];
        ss[t] = s * 0.125f;
    }
    __syncthreads();
    if (t < 64) {
        int jj = t >> 3;
        float nsq = 0.f;
        #pragma unroll
        for (int mm = 0; mm < 8; mm++) { float v = ss[jj * 8 + mm]; nsq = fmaf(v, v, nsq); }
        float n = sqrtf(nsq);
        v1s[t] = ss[t] * (n / (1.f + nsq));
    }
    if (t < 80) bs_s[t] = 0.f;
    __syncthreads();

    bool act = (t < 160);
    int jraw = t >> 4;
    int j = (jraw < 10) ? jraw : 0;
    int m = t & 15;

    float u2r[8];
    const float4* W2v = (const float4*)W2;
    const float4* v1v = (const float4*)v1s;
    #pragma unroll
    for (int k = 0; k < 8; k++) {
        int base = ((j * 8 + k) * 16 + m) * 2;
        float4 wa = W2v[base], wb = W2v[base + 1];
        float4 va = v1v[k * 2], vb = v1v[k * 2 + 1];
        u2r[k] = wa.x * va.x + wa.y * va.y + wa.z * va.z + wa.w * va.w
               + wb.x * vb.x + wb.y * vb.y + wb.z * vb.z + wb.w * vb.w;
        if (act) u2s[(j * 8 + k) * 17 + m] = u2r[k];
    }
    __syncthreads();

    float v = 0.f;
    for (int it = 0; it < 3; it++) {
        if (t < 80) es[t] = __expf(bs_s[t]);
        __syncthreads();
        if (t < 8) {
            float d = 0.f;
            #pragma unroll
            for (int jj = 0; jj < 10; jj++) d += es[jj * 8 + t];
            ids[t] = 1.f / d;
        }
        __syncthreads();
        float s = 0.f;
        #pragma unroll
        for (int k = 0; k < 8; k++)
            s = fmaf(es[j * 8 + k] * ids[k], u2r[k], s);
        float p = s * s;
        p += __shfl_xor_sync(0xffffffffu, p, 1);
        p += __shfl_xor_sync(0xffffffffu, p, 2);
        p += __shfl_xor_sync(0xffffffffu, p, 4);
        p += __shfl_xor_sync(0xffffffffu, p, 8);
        float n = sqrtf(p);
        v = s * (n / (1.f + p));
        if (act) vs[t] = v;
        __syncthreads();
        if (it < 2) {
            if (t < 80) {
                const float* uv = &u2s[t * 17];
                const float* vv = &vs[(t >> 3) * 16];
                float q = 0.f;
                #pragma unroll
                for (int mm = 0; mm < 16; mm++) q = fmaf(uv[mm], vv[mm], q);
                bs_s[t] += q;
            }
            __syncthreads();
        }
    }

    if (act) out[b * 160 + t] = v;
}

// ---------------------------------------------------------------------------
extern "C" void kernel_launch(void* const* d_in, const int* in_sizes, int n_in,
                              void* d_out, int out_size)
{
    const float* x      = (const float*)d_in[0];  // [64,1,28,28]
    const float* conv_w = (const float*)d_in[1];  // [32,1,9,9]
    const float* conv_b = (const float*)d_in[2];  // [32]
    const float* W1     = (const float*)d_in[3];  // [8,12800,8,32]
    const float* W2     = (const float*)d_in[4];  // [10,8,16,8]
    float* out = (float*)d_out;                   // [64,10,16]

    cudaFuncSetAttribute(mega_kernel,
                         cudaFuncAttributeMaxDynamicSharedMemorySize,
                         SM_TOTAL * 4);

    mega_kernel<<<NKT, 512, SM_TOTAL * 4>>>(x, conv_w, conv_b, W1, conv_w ? (const float*)d_in[4] : W2, out);
}

// round 15
// speedup vs baseline: 1.0697x; 1.0697x over previous
#include <cuda_runtime.h>
#include <cuda_bf16.h>
#include <cstdint>

// ---------------------------------------------------------------------------
// CapsuleNetwork forward, reset + persistent mega kernel:
//  reset : zero the per-launch ticket/done counters (graph-replay safe).
//  mega  : grid 296 (exactly 2 blocks/SM, even per-SM load), 512 threads.
//          Dynamic ticket loop over 320 tiles (KT=40 = one channel, 2 rows):
//           - in-smem conv for the tile's xf
//           - stream W1 slab (327KB), c-reduce -> ws
//           - GEMM [64b x 64jm] -> g_part[b][tile][jm]  (fixed slot ->
//             bit-deterministic regardless of scheduling)
//          Blocks 0..63 then spin for g_done==320 and finalize batch b:
//          contiguous reduce + squash + digit caps + routing(3) -> out.
// ---------------------------------------------------------------------------

#define B_SZ 64
#define IN_UNITS 12800      // 32*20*20
#define KT 40               // k per tile = 2 rows x 20
#define NKT 320             // 12800 / 40
#define GRID_M 296          // 2 per SM on 148 SMs

__device__ float g_part[B_SZ * NKT * 64];    // 5.24 MB [b][kt][jm]
__device__ int   g_ticket;
__device__ int   g_done;

// dynamic smem layout (floats)
#define SM_IMG   0                    // [64][284]  10 rows x 28 + pad
#define SM_XST   18176                // [40][68]   xf tile transposed [kk][b]
#define SM_WS    20896                // [40][68]   wsum tile [kk][jm]
#define SM_WSM   23616                // [82]       conv weights + bias
#define SM_TOTAL 23698                // floats -> 94792 bytes

__global__ void reset_kernel()
{
    g_ticket = 0;
    g_done = 0;
}

__global__ __launch_bounds__(512) void mega_kernel(
    const float* __restrict__ x, const float* __restrict__ w,
    const float* __restrict__ bias, const float* __restrict__ W1,
    const float* __restrict__ W2, float* __restrict__ out)
{
    extern __shared__ float sm[];
    float* img = sm + SM_IMG;
    float* xsT = sm + SM_XST;
    float* ws  = sm + SM_WS;
    float* wsm = sm + SM_WSM;

    __shared__ int tile_s;

    int bid = blockIdx.x;
    int t = threadIdx.x;         // 0..511
    const float4* __restrict__ Wv = (const float4*)W1;

    // ================= dynamic tile loop =================
    int have = 0;
    for (;;) {
        __threadfence();             // publish prev tile's g_part writes
        __syncthreads();
        if (t == 0) {
            if (have) atomicAdd(&g_done, 1);     // release prev tile
            tile_s = atomicAdd(&g_ticket, 1);    // grab next
        }
        __syncthreads();
        int tile = tile_s;
        if (tile >= NKT) break;
        have = 1;

        int c = tile / 10;           // conv channel
        int y0 = (tile % 10) * 2;    // first of 2 output rows
        size_t base0 = (size_t)tile * 2560;      // f4 offset of W1 slab, j=0

        // ---- issue first stream batch early (DRAM busy during conv) ----
        float4 cur[5], nxt[5];
        #pragma unroll
        for (int q = 0; q < 5; q++) cur[q] = Wv[base0 + q * 512 + t];

        // ---- cooperative image rows load: rows y0..y0+9, all 64 b ----
        {
            const float* xb = x + y0 * 28;
            for (int i = t; i < 4480; i += 512) {
                int bb = i / 70, off = (i % 70) * 4;
                *(float4*)&img[bb * 284 + off] = *(const float4*)&xb[bb * 784 + off];
            }
        }
        if (t < 81) wsm[t] = w[c * 81 + t];
        if (t == 81) wsm[81] = bias[c];
        __syncthreads();

        // ---- conv: thread = (b = t>>3, yl = (t>>2)&1, xq = t&3) ----
        {
            int b = t >> 3, yl = (t >> 2) & 1, x0 = (t & 3) * 5;
            float bv = wsm[81];
            float a0 = 0.f, a1 = 0.f, a2 = 0.f, a3 = 0.f, a4 = 0.f;
            const float* ib = &img[b * 284 + yl * 28 + x0];
            #pragma unroll
            for (int i = 0; i < 9; i++) {
                float wr[9];
                #pragma unroll
                for (int jj = 0; jj < 9; jj++) wr[jj] = wsm[i * 9 + jj];
                float xr[13];
                #pragma unroll
                for (int u = 0; u < 13; u++) xr[u] = ib[i * 28 + u];
                #pragma unroll
                for (int jj = 0; jj < 9; jj++) {
                    a0 = fmaf(xr[0 + jj], wr[jj], a0);
                    a1 = fmaf(xr[1 + jj], wr[jj], a1);
                    a2 = fmaf(xr[2 + jj], wr[jj], a2);
                    a3 = fmaf(xr[3 + jj], wr[jj], a3);
                    a4 = fmaf(xr[4 + jj], wr[jj], a4);
                }
            }
            int kk0 = yl * 20 + x0;
            xsT[(kk0 + 0) * 68 + b] = fmaxf(a0 + bv, 0.f);
            xsT[(kk0 + 1) * 68 + b] = fmaxf(a1 + bv, 0.f);
            xsT[(kk0 + 2) * 68 + b] = fmaxf(a2 + bv, 0.f);
            xsT[(kk0 + 3) * 68 + b] = fmaxf(a3 + bv, 0.f);
            xsT[(kk0 + 4) * 68 + b] = fmaxf(a4 + bv, 0.f);
        }

        // ---- W1 stream, 8 j batches, prefetch-pipelined; c-reduce -> ws ----
        int lanec = t & 7;
        #pragma unroll
        for (int j = 0; j < 8; j++) {
            if (j < 7) {
                size_t nb = base0 + (size_t)(j + 1) * 819200;
                #pragma unroll
                for (int q = 0; q < 5; q++) nxt[q] = Wv[nb + q * 512 + t];
            }
            #pragma unroll
            for (int q = 0; q < 5; q++) {
                float p = (cur[q].x + cur[q].y) + (cur[q].z + cur[q].w);
                p += __shfl_xor_sync(0xffffffffu, p, 1);
                p += __shfl_xor_sync(0xffffffffu, p, 2);
                p += __shfl_xor_sync(0xffffffffu, p, 4);
                if (lanec == 0) {
                    int r = (q * 512 + t) >> 3;        // kk*8 + m
                    ws[(r >> 3) * 68 + j * 8 + (r & 7)] = p;
                }
            }
            if (j < 7) {
                #pragma unroll
                for (int q = 0; q < 5; q++) cur[q] = nxt[q];
            }
        }
        __syncthreads();

        // ---- GEMM [64b x 64jm] over 40 k ----
        {
            int bq  = t >> 5;     // 0..15 -> b = 4*bq..
            int jm2 = t & 31;     // 0..31 -> jm = 2*jm2..

            float a0 = 0.f, a1 = 0.f, a2 = 0.f, a3 = 0.f;
            float a4 = 0.f, a5 = 0.f, a6 = 0.f, a7 = 0.f;

            #pragma unroll
            for (int kk = 0; kk < KT; kk++) {
                float4 xv = *(const float4*)&xsT[kk * 68 + bq * 4];
                float2 wv = *(const float2*)&ws[kk * 68 + jm2 * 2];
                a0 = fmaf(xv.x, wv.x, a0);
                a1 = fmaf(xv.y, wv.x, a1);
                a2 = fmaf(xv.z, wv.x, a2);
                a3 = fmaf(xv.w, wv.x, a3);
                a4 = fmaf(xv.x, wv.y, a4);
                a5 = fmaf(xv.y, wv.y, a5);
                a6 = fmaf(xv.z, wv.y, a6);
                a7 = fmaf(xv.w, wv.y, a7);
            }

            // g_part [b][tile][jm] : index = b*20480 + tile*64 + jm
            int col = jm2 * 2;
            float* dst = &g_part[(size_t)tile * 64 + col];
            dst[(size_t)(bq * 4 + 0) * 20480]     = a0;
            dst[(size_t)(bq * 4 + 1) * 20480]     = a1;
            dst[(size_t)(bq * 4 + 2) * 20480]     = a2;
            dst[(size_t)(bq * 4 + 3) * 20480]     = a3;
            dst[(size_t)(bq * 4 + 0) * 20480 + 1] = a4;
            dst[(size_t)(bq * 4 + 1) * 20480 + 1] = a5;
            dst[(size_t)(bq * 4 + 2) * 20480 + 1] = a6;
            dst[(size_t)(bq * 4 + 3) * 20480 + 1] = a7;
        }
    }

    if (bid >= B_SZ) return;                  // only blocks 0..63 finalize

    // ---- acquire: wait for all 320 tiles of this launch ----
    if (t == 0) {
        while (*((volatile int*)&g_done) < NKT) { }
        __threadfence();
    }
    __syncthreads();

    // ---- finalize batch b = bid ----
    int b = bid;
    float* red  = sm;             // [32][68]
    float* ss   = sm + 2176;      // 64
    float* v1s  = sm + 2240;      // 64
    float* u2s  = sm + 2304;      // [80][17]
    float* vs   = sm + 3664;      // 160
    float* es   = sm + 3824;      // 80
    float* bs_s = sm + 3904;      // 80
    float* ids  = sm + 3984;      // 8

    // contiguous reduce of g_part[b][320][64]: thread=(g in 32, c4 in 16)
    {
        int c4 = t & 15, g = t >> 4;
        const float* src = &g_part[(size_t)b * 20480 + c4 * 4];
        float4 acc = make_float4(0.f, 0.f, 0.f, 0.f);
        #pragma unroll
        for (int q = 0; q < 10; q++) {
            float4 v = *(const float4*)&src[(size_t)(g + 32 * q) * 64];
            acc.x += v.x; acc.y += v.y; acc.z += v.z; acc.w += v.w;
        }
        red[g * 68 + c4 * 4 + 0] = acc.x;
        red[g * 68 + c4 * 4 + 1] = acc.y;
        red[g * 68 + c4 * 4 + 2] = acc.z;
        red[g * 68 + c4 * 4 + 3] = acc.w;
    }
    __syncthreads();
    if (t < 64) {
        float s = 0.f;
        #pragma unroll
        for (int i = 0; i < 32; i++) s += red[i * 68 + t];
        ss[t] = s * 0.125f;
    }
    __syncthreads();
    if (t < 64) {
        int jj = t >> 3;
        float nsq = 0.f;
        #pragma unroll
        for (int mm = 0; mm < 8; mm++) { float v = ss[jj * 8 + mm]; nsq = fmaf(v, v, nsq); }
        float n = sqrtf(nsq);
        v1s[t] = ss[t] * (n / (1.f + nsq));
    }
    if (t < 80) bs_s[t] = 0.f;
    __syncthreads();

    bool act = (t < 160);
    int jraw = t >> 4;
    int j = (jraw < 10) ? jraw : 0;
    int m = t & 15;

    float u2r[8];
    const float4* W2v = (const float4*)W2;
    const float4* v1v = (const float4*)v1s;
    #pragma unroll
    for (int k = 0; k < 8; k++) {
        int base = ((j * 8 + k) * 16 + m) * 2;
        float4 wa = W2v[base], wb = W2v[base + 1];
        float4 va = v1v[k * 2], vb = v1v[k * 2 + 1];
        u2r[k] = wa.x * va.x + wa.y * va.y + wa.z * va.z + wa.w * va.w
               + wb.x * vb.x + wb.y * vb.y + wb.z * vb.z + wb.w * vb.w;
        if (act) u2s[(j * 8 + k) * 17 + m] = u2r[k];
    }
    __syncthreads();

    float v = 0.f;
    for (int it = 0; it < 3; it++) {
        if (t < 80) es[t] = __expf(bs_s[t]);
        __syncthreads();
        if (t < 8) {
            float d = 0.f;
            #pragma unroll
            for (int jj = 0; jj < 10; jj++) d += es[jj * 8 + t];
            ids[t] = 1.f / d;
        }
        __syncthreads();
        float s = 0.f;
        #pragma unroll
        for (int k = 0; k < 8; k++)
            s = fmaf(es[j * 8 + k] * ids[k], u2r[k], s);
        float p = s * s;
        p += __shfl_xor_sync(0xffffffffu, p, 1);
        p += __shfl_xor_sync(0xffffffffu, p, 2);
        p += __shfl_xor_sync(0xffffffffu, p, 4);
        p += __shfl_xor_sync(0xffffffffu, p, 8);
        float n = sqrtf(p);
        v = s * (n / (1.f + p));
        if (act) vs[t] = v;
        __syncthreads();
        if (it < 2) {
            if (t < 80) {
                const float* uv = &u2s[t * 17];
                const float* vv = &vs[(t >> 3) * 16];
                float q = 0.f;
                #pragma unroll
                for (int mm = 0; mm < 16; mm++) q = fmaf(uv[mm], vv[mm], q);
                bs_s[t] += q;
            }
            __syncthreads();
        }
    }

    if (act) out[b * 160 + t] = v;
}

// ---------------------------------------------------------------------------
extern "C" void kernel_launch(void* const* d_in, const int* in_sizes, int n_in,
                              void* d_out, int out_size)
{
    const float* x      = (const float*)d_in[0];  // [64,1,28,28]
    const float* conv_w = (const float*)d_in[1];  // [32,1,9,9]
    const float* conv_b = (const float*)d_in[2];  // [32]
    const float* W1     = (const float*)d_in[3];  // [8,12800,8,32]
    const float* W2     = (const float*)d_in[4];  // [10,8,16,8]
    float* out = (float*)d_out;                   // [64,10,16]

    cudaFuncSetAttribute(mega_kernel,
                         cudaFuncAttributeMaxDynamicSharedMemorySize,
                         SM_TOTAL * 4);

    reset_kernel<<<1, 1>>>();
    mega_kernel<<<GRID_M, 512, SM_TOTAL * 4>>>(x, conv_w, conv_b, W1, W2, out);
}